// round 3
// baseline (speedup 1.0000x reference)
#include <cuda_runtime.h>
#include <cuda.h>
#include <cuda_bf16.h>
#include <math.h>
#include <stdint.h>

// ============================================================
// Problem constants
// ============================================================
#define IGNORE_INDEX (-100)
#define N_TOK   8192
#define DIM     2048
#define VOCAB   32000

#define TILE_M  128
#define TILE_V  128
#define TILE_K  64
#define NM_TILES (N_TOK / TILE_M)   // 64
#define NV_TILES (VOCAB / TILE_V)   // 250
#define NKITER   (DIM / TILE_K)     // 32
#define STAGES   4

// Per-warp tile: 64 (M) x 32 (V). 2x4 warp grid.
#define WARP_M 64
#define WARP_V 32
#define NV_P   (NV_TILES * 4)       // 1000 vocab strips of 32 cols

#define A_STAGE_BYTES (TILE_M * TILE_K * 2)   // 16384
#define B_STAGE_BYTES (TILE_V * TILE_K * 2)   // 16384
#define STAGE_BYTES   (A_STAGE_BYTES + B_STAGE_BYTES)
#define SMEM_A_OFF 1024
#define SMEM_B_OFF (SMEM_A_OFF + STAGES * A_STAGE_BYTES)
#define SMEM_TOTAL (SMEM_B_OFF + STAGES * B_STAGE_BYTES)   // 132096

// ============================================================
// Device-global scratch
// ============================================================
__device__ __nv_bfloat162 g_hbf[N_TOK * DIM / 2];     // 32 MB
__device__ __nv_bfloat162 g_wbf[VOCAB * DIM / 2];     // 131 MB
__device__ float g_part_m[NV_P * N_TOK];              // 32.8 MB
__device__ float g_part_s[NV_P * N_TOK];              // 32.8 MB
__device__ float g_tgt_logit[N_TOK];
__device__ int   g_valid[N_TOK];
__device__ int   g_is64;
__device__ double g_sum;
__device__ int    g_cnt;

// ============================================================
// PTX helpers
// ============================================================
__device__ __forceinline__ uint32_t smem_to_u32(const void* p) {
    uint32_t a;
    asm("{ .reg .u64 t; cvta.to.shared.u64 t, %1; cvt.u32.u64 %0, t; }" : "=r"(a) : "l"(p));
    return a;
}

#define MBARRIER_INIT(addr, cnt) \
    asm volatile("mbarrier.init.shared.b64 [%0], %1;" :: "r"((uint32_t)(addr)), "r"((uint32_t)(cnt)) : "memory")
#define MBARRIER_EXPECT_TX(addr, tx) \
    asm volatile("mbarrier.arrive.expect_tx.shared.b64 _, [%0], %1;" :: "r"((uint32_t)(addr)), "r"((uint32_t)(tx)) : "memory")

#define MBARRIER_WAIT_PARITY(mbar_smem_addr, phase_parity) do { \
    uint32_t _mbar = (uint32_t)(mbar_smem_addr); \
    uint32_t _parity = (uint32_t)(phase_parity); \
    uint32_t _done; \
    asm volatile("{\n\t.reg .pred p;\n\t" \
        "mbarrier.try_wait.parity.acquire.cta.shared::cta.b64 p, [%1], %2;\n\t" \
        "selp.b32 %0, 1, 0, p;\n\t}" \
        : "=r"(_done) : "r"(_mbar), "r"(_parity) : "memory"); \
    if (!_done) { \
        asm volatile("{\n\t.reg .pred P1;\n\t" \
            "WAIT_LOOP_%=:\n\t" \
            "mbarrier.try_wait.parity.acquire.cta.shared::cta.b64 P1, [%0], %1, 0x989680;\n\t" \
            "@P1 bra.uni WAIT_DONE_%=;\n\t" \
            "bra.uni WAIT_LOOP_%=;\n\t" \
            "WAIT_DONE_%=:\n\t}" \
            :: "r"(_mbar), "r"(_parity) : "memory"); \
    } \
} while(0)

#define TMA_LOAD_2D(smem_addr, map_ptr, cx, cy, mbar) \
    asm volatile("cp.async.bulk.tensor.2d.shared::cta.global.tile.mbarrier::complete_tx::bytes " \
        "[%0], [%1, {%2, %3}], [%4];" \
        :: "r"((uint32_t)(smem_addr)), "l"(map_ptr), "r"((int)(cx)), "r"((int)(cy)), \
           "r"((uint32_t)(mbar)) : "memory")

#define SW128(off) ((off) ^ (((off) >> 3) & 0x70))

__device__ __forceinline__ void ldmatrix_x4(uint32_t& r0, uint32_t& r1, uint32_t& r2, uint32_t& r3,
                                            uint32_t addr) {
    asm volatile("ldmatrix.sync.aligned.m8n8.x4.shared.b16 {%0,%1,%2,%3}, [%4];"
        : "=r"(r0), "=r"(r1), "=r"(r2), "=r"(r3) : "r"(addr));
}

__device__ __forceinline__ void mma_bf16(float* c, const uint32_t* a, const uint32_t* b) {
    asm volatile("mma.sync.aligned.m16n8k16.row.col.f32.bf16.bf16.f32 "
        "{%0,%1,%2,%3}, {%4,%5,%6,%7}, {%8,%9}, {%0,%1,%2,%3};"
        : "+f"(c[0]), "+f"(c[1]), "+f"(c[2]), "+f"(c[3])
        : "r"(a[0]), "r"(a[1]), "r"(a[2]), "r"(a[3]), "r"(b[0]), "r"(b[1]));
}

// ============================================================
// Kernel 1: detect target dtype (int64 vs int32) + zero accumulators
// ============================================================
__global__ void detect_zero_kernel(const int* t32) {
    if (threadIdx.x == 0) {
        int is64 = 1;
        for (int i = 1; i < 512; i += 2) {
            int v = t32[i];
            if (v != 0 && v != -1) { is64 = 0; break; }
        }
        g_is64 = is64;
        g_sum = 0.0;
        g_cnt = 0;
    }
}

// ============================================================
// Kernel 2: fp32 -> bf16 conversion of hidden + weight
// ============================================================
__global__ void convert_kernel(const float4* __restrict__ h, const float4* __restrict__ w) {
    const int NH4 = N_TOK * DIM / 4;
    const int NW4 = VOCAB * DIM / 4;
    for (int i = blockIdx.x * blockDim.x + threadIdx.x; i < NH4 + NW4;
         i += gridDim.x * blockDim.x) {
        float4 v;
        __nv_bfloat162* dst;
        if (i < NH4) { v = h[i]; dst = &g_hbf[i * 2]; }
        else         { int j = i - NH4; v = w[j]; dst = &g_wbf[j * 2]; }
        dst[0] = __floats2bfloat162_rn(v.x, v.y);
        dst[1] = __floats2bfloat162_rn(v.z, v.w);
    }
}

// ============================================================
// Kernel 3: exact fp32 target logit per token
// ============================================================
__global__ void tgt_logit_kernel(const float* __restrict__ hidden,
                                 const float* __restrict__ weight,
                                 const void* __restrict__ targets) {
    int n = blockIdx.x;
    long long t;
    if (g_is64) t = ((const long long*)targets)[n];
    else        t = (long long)((const int*)targets)[n];
    bool valid = (t != IGNORE_INDEX) && (t >= 0) && (t < VOCAB);
    if (!valid) {
        if (threadIdx.x == 0) { g_tgt_logit[n] = 0.f; g_valid[n] = 0; }
        return;
    }
    const float4* hv = (const float4*)(hidden + (size_t)n * DIM);
    const float4* wv = (const float4*)(weight + (size_t)t * DIM);
    float acc = 0.f;
    for (int i = threadIdx.x; i < DIM / 4; i += blockDim.x) {
        float4 a = hv[i], b = wv[i];
        acc += a.x * b.x + a.y * b.y + a.z * b.z + a.w * b.w;
    }
    #pragma unroll
    for (int o = 16; o; o >>= 1) acc += __shfl_xor_sync(0xffffffffu, acc, o);
    __shared__ float ws[8];
    if ((threadIdx.x & 31) == 0) ws[threadIdx.x >> 5] = acc;
    __syncthreads();
    if (threadIdx.x == 0) {
        float s = 0.f;
        for (int w2 = 0; w2 < (int)(blockDim.x >> 5); w2++) s += ws[w2];
        g_tgt_logit[n] = s;
        g_valid[n] = 1;
    }
}

// ============================================================
// Kernel 4: TMA-pipelined bf16 HMMA GEMM (128x128x64) + fused online LSE
// ============================================================
__global__ __launch_bounds__(256, 1)
void gemm_lse_kernel(const __grid_constant__ CUtensorMap tmapA,
                     const __grid_constant__ CUtensorMap tmapB) {
    extern __shared__ char smem[];
    const uint32_t sb = smem_to_u32(smem);
    const int tid = threadIdx.x;
    const int wid = tid >> 5;
    const int lid = tid & 31;
    const int warp_m = wid >> 2;          // 0..1
    const int warp_n = wid & 3;           // 0..3

    if (tid == 0) {
        #pragma unroll
        for (int s = 0; s < STAGES; s++) MBARRIER_INIT(sb + s * 8, 1);
    }
    __syncthreads();

    const int m0 = blockIdx.x * TILE_M;
    const int vt = blockIdx.y;
    const int v0 = vt * TILE_V;

    // Prologue: fill all stages
    if (tid == 0) {
        #pragma unroll
        for (int s = 0; s < STAGES; s++) {
            MBARRIER_EXPECT_TX(sb + s * 8, STAGE_BYTES);
            TMA_LOAD_2D(sb + SMEM_A_OFF + s * A_STAGE_BYTES, &tmapA, s * TILE_K, m0, sb + s * 8);
            TMA_LOAD_2D(sb + SMEM_B_OFF + s * B_STAGE_BYTES, &tmapB, s * TILE_K, v0, sb + s * 8);
        }
    }

    // Per-lane ldmatrix base offsets (unswizzled, k0=0)
    const int tIdx = lid >> 3;            // 0..3
    const int rIn  = lid & 7;
    const int rowA0 = warp_m * WARP_M + (tIdx & 1) * 8 + rIn;   // + mt*16
    const int rowB0 = warp_n * WARP_V + (tIdx & 1) * 8 + rIn;   // + p*16
    const int colHalf = (tIdx >> 1) * 8;                         // bf16 col offset

    float c[4][4][4];
    #pragma unroll
    for (int i = 0; i < 4; i++)
        #pragma unroll
        for (int j = 0; j < 4; j++)
            #pragma unroll
            for (int q = 0; q < 4; q++) c[i][j][q] = 0.f;

    for (int it = 0; it < NKITER; it++) {
        const int s = it & (STAGES - 1);
        const int ph = (it / STAGES) & 1;
        MBARRIER_WAIT_PARITY(sb + s * 8, ph);

        const uint32_t aBase = sb + SMEM_A_OFF + s * A_STAGE_BYTES;
        const uint32_t bBase = sb + SMEM_B_OFF + s * B_STAGE_BYTES;

        #pragma unroll
        for (int ks = 0; ks < TILE_K / 16; ks++) {
            const int kc = ks * 16 + colHalf;        // bf16 col for this lane
            // A fragments: 4 m-tiles
            uint32_t a[4][4];
            #pragma unroll
            for (int mt = 0; mt < 4; mt++) {
                uint32_t off = (uint32_t)((rowA0 + mt * 16) * 128 + kc * 2);
                ldmatrix_x4(a[mt][0], a[mt][1], a[mt][2], a[mt][3], aBase + SW128(off));
            }
            // B fragments: 2 pair-loads covering 4 n-tiles
            uint32_t bb[2][4];
            #pragma unroll
            for (int p = 0; p < 2; p++) {
                uint32_t off = (uint32_t)((rowB0 + p * 16) * 128 + kc * 2);
                ldmatrix_x4(bb[p][0], bb[p][1], bb[p][2], bb[p][3], bBase + SW128(off));
            }
            uint32_t bf[4][2];
            #pragma unroll
            for (int p = 0; p < 2; p++) {
                bf[2*p  ][0] = bb[p][0]; bf[2*p  ][1] = bb[p][2];
                bf[2*p+1][0] = bb[p][1]; bf[2*p+1][1] = bb[p][3];
            }
            #pragma unroll
            for (int mt = 0; mt < 4; mt++)
                #pragma unroll
                for (int nt = 0; nt < 4; nt++)
                    mma_bf16(c[mt][nt], a[mt], bf[nt]);
        }

        __syncthreads();   // all warps done reading slot s
        if (tid == 0 && it + STAGES < NKITER) {
            MBARRIER_EXPECT_TX(sb + s * 8, STAGE_BYTES);
            TMA_LOAD_2D(sb + SMEM_A_OFF + s * A_STAGE_BYTES, &tmapA, (it + STAGES) * TILE_K, m0, sb + s * 8);
            TMA_LOAD_2D(sb + SMEM_B_OFF + s * B_STAGE_BYTES, &tmapB, (it + STAGES) * TILE_K, v0, sb + s * 8);
        }
    }

    // ---- Epilogue: per-row (max, sum-exp) over this CTA's 32-col strip per warp ----
    const int g = lid >> 2;
    #pragma unroll
    for (int mt = 0; mt < 4; mt++) {
        #pragma unroll
        for (int half = 0; half < 2; half++) {
            float m = -INFINITY;
            #pragma unroll
            for (int nt = 0; nt < 4; nt++) {
                m = fmaxf(m, c[mt][nt][half * 2]);
                m = fmaxf(m, c[mt][nt][half * 2 + 1]);
            }
            float ssum = 0.f;
            #pragma unroll
            for (int nt = 0; nt < 4; nt++) {
                ssum += __expf(c[mt][nt][half * 2]     - m);
                ssum += __expf(c[mt][nt][half * 2 + 1] - m);
            }
            // quad reduce (lanes sharing the same row: lane%4 varies)
            #pragma unroll
            for (int off = 1; off <= 2; off <<= 1) {
                float om = __shfl_xor_sync(0xffffffffu, m, off);
                float os = __shfl_xor_sync(0xffffffffu, ssum, off);
                float nm = fmaxf(m, om);
                ssum = ssum * __expf(m - nm) + os * __expf(om - nm);
                m = nm;
            }
            if ((lid & 3) == 0) {
                int row = m0 + warp_m * WARP_M + mt * 16 + half * 8 + g;
                int pcol = vt * 4 + warp_n;
                g_part_m[pcol * N_TOK + row] = m;
                g_part_s[pcol * N_TOK + row] = ssum;
            }
        }
    }
}

// ============================================================
// Kernel 5: combine per-strip partials -> per-row NLL -> global sum
// ============================================================
__global__ void reduce_rows_kernel() {
    int n = blockIdx.x * blockDim.x + threadIdx.x;   // 8192 threads
    float nll = 0.f;
    int c = 0;
    if (n < N_TOK && g_valid[n]) {
        float m = -INFINITY;
        for (int j = 0; j < NV_P; j++) m = fmaxf(m, g_part_m[j * N_TOK + n]);
        float s = 0.f;
        for (int j = 0; j < NV_P; j++)
            s += g_part_s[j * N_TOK + n] * __expf(g_part_m[j * N_TOK + n] - m);
        nll = m + logf(s) - g_tgt_logit[n];
        c = 1;
    }
    #pragma unroll
    for (int o = 16; o; o >>= 1) {
        nll += __shfl_xor_sync(0xffffffffu, nll, o);
        c   += __shfl_xor_sync(0xffffffffu, c, o);
    }
    __shared__ float sm[8];
    __shared__ int   sc[8];
    if ((threadIdx.x & 31) == 0) { sm[threadIdx.x >> 5] = nll; sc[threadIdx.x >> 5] = c; }
    __syncthreads();
    if (threadIdx.x == 0) {
        float t = 0.f; int tc = 0;
        for (int w = 0; w < 8; w++) { t += sm[w]; tc += sc[w]; }
        atomicAdd(&g_sum, (double)t);
        atomicAdd(&g_cnt, tc);
    }
}

// ============================================================
// Kernel 6: final division
// ============================================================
__global__ void final_kernel(float* out) {
    out[0] = (g_cnt > 0) ? (float)(g_sum / (double)g_cnt) : 0.f;
}

// ============================================================
// Host launcher
// ============================================================
typedef CUresult (*PFN_encodeTiled)(
    CUtensorMap*, CUtensorMapDataType, cuuint32_t, void*,
    const cuuint64_t*, const cuuint64_t*, const cuuint32_t*, const cuuint32_t*,
    CUtensorMapInterleave, CUtensorMapSwizzle, CUtensorMapL2promotion, CUtensorMapFloatOOBfill);

extern "C" void kernel_launch(void* const* d_in, const int* in_sizes, int n_in,
                              void* d_out, int out_size) {
    const float* d_hidden  = (const float*)d_in[0];
    const void*  d_targets = d_in[1];
    const float* d_weight  = (const float*)d_in[2];
    float* out = (float*)d_out;

    void* pA = nullptr; cudaGetSymbolAddress(&pA, g_hbf);
    void* pB = nullptr; cudaGetSymbolAddress(&pB, g_wbf);

    PFN_encodeTiled encode = nullptr;
    {
        void* fp = nullptr;
        cudaDriverEntryPointQueryResult qres;
        cudaGetDriverEntryPoint("cuTensorMapEncodeTiled", &fp, cudaEnableDefault, &qres);
        encode = (PFN_encodeTiled)fp;
    }

    CUtensorMap mapA, mapB;
    {
        cuuint64_t dims[2]  = { DIM, N_TOK };
        cuuint64_t strd[1]  = { DIM * 2 };
        cuuint32_t box[2]   = { TILE_K, TILE_M };
        cuuint32_t es[2]    = { 1, 1 };
        encode(&mapA, CU_TENSOR_MAP_DATA_TYPE_BFLOAT16, 2, pA, dims, strd, box, es,
               CU_TENSOR_MAP_INTERLEAVE_NONE, CU_TENSOR_MAP_SWIZZLE_128B,
               CU_TENSOR_MAP_L2_PROMOTION_L2_128B, CU_TENSOR_MAP_FLOAT_OOB_FILL_NONE);
    }
    {
        cuuint64_t dims[2]  = { DIM, VOCAB };
        cuuint64_t strd[1]  = { DIM * 2 };
        cuuint32_t box[2]   = { TILE_K, TILE_V };
        cuuint32_t es[2]    = { 1, 1 };
        encode(&mapB, CU_TENSOR_MAP_DATA_TYPE_BFLOAT16, 2, pB, dims, strd, box, es,
               CU_TENSOR_MAP_INTERLEAVE_NONE, CU_TENSOR_MAP_SWIZZLE_128B,
               CU_TENSOR_MAP_L2_PROMOTION_L2_128B, CU_TENSOR_MAP_FLOAT_OOB_FILL_NONE);
    }

    cudaFuncSetAttribute(gemm_lse_kernel, cudaFuncAttributeMaxDynamicSharedMemorySize, SMEM_TOTAL);

    detect_zero_kernel<<<1, 32>>>((const int*)d_targets);
    convert_kernel<<<1184, 256>>>((const float4*)d_hidden, (const float4*)d_weight);
    tgt_logit_kernel<<<N_TOK, 256>>>(d_hidden, d_weight, d_targets);
    gemm_lse_kernel<<<dim3(NM_TILES, NV_TILES), 256, SMEM_TOTAL>>>(mapA, mapB);
    reduce_rows_kernel<<<32, 256>>>();
    final_kernel<<<1, 1>>>(out);
}

// round 4
// speedup vs baseline: 1.1396x; 1.1396x over previous
#include <cuda_runtime.h>
#include <cuda.h>
#include <cuda_bf16.h>
#include <math.h>
#include <stdint.h>

// ============================================================
// Problem constants
// ============================================================
#define IGNORE_INDEX (-100)
#define N_TOK   8192
#define DIM     2048
#define VOCAB   32000

#define TILE_M  128
#define TILE_V  128
#define TILE_K  64
#define NM_TILES (N_TOK / TILE_M)   // 64
#define NV_TILES (VOCAB / TILE_V)   // 250
#define NKITER   (DIM / TILE_K)     // 32
#define STAGES   3

// Per-warp tile: 64 (M) x 32 (V). 2x4 warp grid.
#define WARP_M 64
#define WARP_V 32
#define NV_P   (NV_TILES * 4)       // 1000 vocab strips of 32 cols

#define A_STAGE_BYTES (TILE_M * TILE_K * 2)   // 16384
#define B_STAGE_BYTES (TILE_V * TILE_K * 2)   // 16384
#define STAGE_BYTES   (A_STAGE_BYTES + B_STAGE_BYTES)
#define SMEM_A_OFF 1024
#define SMEM_B_OFF (SMEM_A_OFF + STAGES * A_STAGE_BYTES)
#define SMEM_TOTAL (SMEM_B_OFF + STAGES * B_STAGE_BYTES)   // 99328 (~97KB) -> 2 CTAs/SM

// ============================================================
// Device-global scratch
// ============================================================
__device__ __nv_bfloat162 g_hbf[N_TOK * DIM / 2];     // 32 MB
__device__ __nv_bfloat162 g_wbf[VOCAB * DIM / 2];     // 131 MB
__device__ float g_part_m[NV_P * N_TOK];              // 32.8 MB
__device__ float g_part_s[NV_P * N_TOK];              // 32.8 MB
__device__ float g_tgt_logit[N_TOK];
__device__ int   g_valid[N_TOK];
__device__ int   g_is64;
__device__ double g_sum;
__device__ int    g_cnt;

// ============================================================
// PTX helpers
// ============================================================
__device__ __forceinline__ uint32_t smem_to_u32(const void* p) {
    uint32_t a;
    asm("{ .reg .u64 t; cvta.to.shared.u64 t, %1; cvt.u32.u64 %0, t; }" : "=r"(a) : "l"(p));
    return a;
}

#define MBARRIER_INIT(addr, cnt) \
    asm volatile("mbarrier.init.shared.b64 [%0], %1;" :: "r"((uint32_t)(addr)), "r"((uint32_t)(cnt)) : "memory")
#define MBARRIER_EXPECT_TX(addr, tx) \
    asm volatile("mbarrier.arrive.expect_tx.shared.b64 _, [%0], %1;" :: "r"((uint32_t)(addr)), "r"((uint32_t)(tx)) : "memory")

#define MBARRIER_WAIT_PARITY(mbar_smem_addr, phase_parity) do { \
    uint32_t _mbar = (uint32_t)(mbar_smem_addr); \
    uint32_t _parity = (uint32_t)(phase_parity); \
    uint32_t _done; \
    asm volatile("{\n\t.reg .pred p;\n\t" \
        "mbarrier.try_wait.parity.acquire.cta.shared::cta.b64 p, [%1], %2;\n\t" \
        "selp.b32 %0, 1, 0, p;\n\t}" \
        : "=r"(_done) : "r"(_mbar), "r"(_parity) : "memory"); \
    if (!_done) { \
        asm volatile("{\n\t.reg .pred P1;\n\t" \
            "WAIT_LOOP_%=:\n\t" \
            "mbarrier.try_wait.parity.acquire.cta.shared::cta.b64 P1, [%0], %1, 0x989680;\n\t" \
            "@P1 bra.uni WAIT_DONE_%=;\n\t" \
            "bra.uni WAIT_LOOP_%=;\n\t" \
            "WAIT_DONE_%=:\n\t}" \
            :: "r"(_mbar), "r"(_parity) : "memory"); \
    } \
} while(0)

#define TMA_LOAD_2D(smem_addr, map_ptr, cx, cy, mbar) \
    asm volatile("cp.async.bulk.tensor.2d.shared::cta.global.tile.mbarrier::complete_tx::bytes " \
        "[%0], [%1, {%2, %3}], [%4];" \
        :: "r"((uint32_t)(smem_addr)), "l"(map_ptr), "r"((int)(cx)), "r"((int)(cy)), \
           "r"((uint32_t)(mbar)) : "memory")

__device__ __forceinline__ void ldmatrix_x4(uint32_t& r0, uint32_t& r1, uint32_t& r2, uint32_t& r3,
                                            uint32_t addr) {
    asm volatile("ldmatrix.sync.aligned.m8n8.x4.shared.b16 {%0,%1,%2,%3}, [%4];"
        : "=r"(r0), "=r"(r1), "=r"(r2), "=r"(r3) : "r"(addr));
}

__device__ __forceinline__ void mma_bf16(float* c, const uint32_t* a, const uint32_t* b) {
    asm volatile("mma.sync.aligned.m16n8k16.row.col.f32.bf16.bf16.f32 "
        "{%0,%1,%2,%3}, {%4,%5,%6,%7}, {%8,%9}, {%0,%1,%2,%3};"
        : "+f"(c[0]), "+f"(c[1]), "+f"(c[2]), "+f"(c[3])
        : "r"(a[0]), "r"(a[1]), "r"(a[2]), "r"(a[3]), "r"(b[0]), "r"(b[1]));
}

// ============================================================
// Kernel 1: detect target dtype (int64 vs int32) + zero accumulators
// ============================================================
__global__ void detect_zero_kernel(const int* t32) {
    if (threadIdx.x == 0) {
        int is64 = 1;
        for (int i = 1; i < 512; i += 2) {
            int v = t32[i];
            if (v != 0 && v != -1) { is64 = 0; break; }
        }
        g_is64 = is64;
        g_sum = 0.0;
        g_cnt = 0;
    }
}

// ============================================================
// Kernel 2: fp32 -> bf16 conversion of hidden + weight
// ============================================================
__global__ void convert_kernel(const float4* __restrict__ h, const float4* __restrict__ w) {
    const int NH4 = N_TOK * DIM / 4;
    const int NW4 = VOCAB * DIM / 4;
    for (int i = blockIdx.x * blockDim.x + threadIdx.x; i < NH4 + NW4;
         i += gridDim.x * blockDim.x) {
        float4 v;
        __nv_bfloat162* dst;
        if (i < NH4) { v = h[i]; dst = &g_hbf[i * 2]; }
        else         { int j = i - NH4; v = w[j]; dst = &g_wbf[j * 2]; }
        dst[0] = __floats2bfloat162_rn(v.x, v.y);
        dst[1] = __floats2bfloat162_rn(v.z, v.w);
    }
}

// ============================================================
// Kernel 3: exact fp32 target logit per token
// ============================================================
__global__ void tgt_logit_kernel(const float* __restrict__ hidden,
                                 const float* __restrict__ weight,
                                 const void* __restrict__ targets) {
    int n = blockIdx.x;
    long long t;
    if (g_is64) t = ((const long long*)targets)[n];
    else        t = (long long)((const int*)targets)[n];
    bool valid = (t != IGNORE_INDEX) && (t >= 0) && (t < VOCAB);
    if (!valid) {
        if (threadIdx.x == 0) { g_tgt_logit[n] = 0.f; g_valid[n] = 0; }
        return;
    }
    const float4* hv = (const float4*)(hidden + (size_t)n * DIM);
    const float4* wv = (const float4*)(weight + (size_t)t * DIM);
    float acc = 0.f;
    for (int i = threadIdx.x; i < DIM / 4; i += blockDim.x) {
        float4 a = hv[i], b = wv[i];
        acc += a.x * b.x + a.y * b.y + a.z * b.z + a.w * b.w;
    }
    #pragma unroll
    for (int o = 16; o; o >>= 1) acc += __shfl_xor_sync(0xffffffffu, acc, o);
    __shared__ float ws[8];
    if ((threadIdx.x & 31) == 0) ws[threadIdx.x >> 5] = acc;
    __syncthreads();
    if (threadIdx.x == 0) {
        float s = 0.f;
        for (int w2 = 0; w2 < (int)(blockDim.x >> 5); w2++) s += ws[w2];
        g_tgt_logit[n] = s;
        g_valid[n] = 1;
    }
}

// ============================================================
// Kernel 4: TMA-pipelined bf16 HMMA GEMM (128x128x64) + fused online LSE
//   - swizzle folded into lane constants (no per-load XOR chain)
//   - 3 stages, 2 CTAs/SM
// ============================================================
__global__ __launch_bounds__(256, 2)
void gemm_lse_kernel(const __grid_constant__ CUtensorMap tmapA,
                     const __grid_constant__ CUtensorMap tmapB) {
    extern __shared__ char smem[];
    const uint32_t sb = smem_to_u32(smem);
    const int tid = threadIdx.x;
    const int wid = tid >> 5;
    const int lid = tid & 31;
    const int warp_m = wid >> 2;          // 0..1
    const int warp_n = wid & 3;           // 0..3

    if (tid == 0) {
        #pragma unroll
        for (int s = 0; s < STAGES; s++) MBARRIER_INIT(sb + s * 8, 1);
    }
    __syncthreads();

    const int m0 = blockIdx.x * TILE_M;
    const int vt = blockIdx.y;
    const int v0 = vt * TILE_V;

    // Prologue: fill all stages
    if (tid == 0) {
        #pragma unroll
        for (int s = 0; s < STAGES; s++) {
            MBARRIER_EXPECT_TX(sb + s * 8, STAGE_BYTES);
            TMA_LOAD_2D(sb + SMEM_A_OFF + s * A_STAGE_BYTES, &tmapA, s * TILE_K, m0, sb + s * 8);
            TMA_LOAD_2D(sb + SMEM_B_OFF + s * B_STAGE_BYTES, &tmapB, s * TILE_K, v0, sb + s * 8);
        }
    }

    // Per-lane ldmatrix rows (within tile) and swizzle-folded column constants.
    // For off = row*128 + col2 (col2 < 128): SW128(off) = row*128 + (col2 ^ ((row&7)<<4)).
    // row&7 is invariant under +16 (mt/p steps), so the XOR is a pure lane constant.
    const int tIdx = lid >> 3;            // 0..3
    const int rIn  = lid & 7;
    const int rowA0 = warp_m * WARP_M + (tIdx & 1) * 8 + rIn;   // + mt*16
    const int rowB0 = warp_n * WARP_V + (tIdx & 1) * 8 + rIn;   // + p*16
    const int colHalf2 = (tIdx >> 1) * 16;                       // byte offset of 8-col half

    const uint32_t xorA = (uint32_t)((rowA0 & 7) << 4);
    const uint32_t xorB = (uint32_t)((rowB0 & 7) << 4);
    uint32_t cA[4], cB[4];
    #pragma unroll
    for (int ks = 0; ks < 4; ks++) {
        cA[ks] = ((uint32_t)(ks * 32 + colHalf2)) ^ xorA;
        cB[ks] = ((uint32_t)(ks * 32 + colHalf2)) ^ xorB;
    }
    const uint32_t aLane = sb + SMEM_A_OFF + (uint32_t)rowA0 * 128;
    const uint32_t bLane = sb + SMEM_B_OFF + (uint32_t)rowB0 * 128;

    float c[4][4][4];
    #pragma unroll
    for (int i = 0; i < 4; i++)
        #pragma unroll
        for (int j = 0; j < 4; j++)
            #pragma unroll
            for (int q = 0; q < 4; q++) c[i][j][q] = 0.f;

    for (int it = 0; it < NKITER; it++) {
        const int s = it % STAGES;
        const int ph = (it / STAGES) & 1;
        MBARRIER_WAIT_PARITY(sb + s * 8, ph);

        const uint32_t aS = aLane + s * A_STAGE_BYTES;
        const uint32_t bS = bLane + s * B_STAGE_BYTES;

        #pragma unroll
        for (int ks = 0; ks < TILE_K / 16; ks++) {
            // A fragments: 4 m-tiles
            uint32_t a[4][4];
            #pragma unroll
            for (int mt = 0; mt < 4; mt++)
                ldmatrix_x4(a[mt][0], a[mt][1], a[mt][2], a[mt][3],
                            aS + (uint32_t)(mt * 16 * 128) + cA[ks]);
            // B fragments: 2 pair-loads covering 4 n-tiles
            uint32_t bb[2][4];
            #pragma unroll
            for (int p = 0; p < 2; p++)
                ldmatrix_x4(bb[p][0], bb[p][1], bb[p][2], bb[p][3],
                            bS + (uint32_t)(p * 16 * 128) + cB[ks]);
            uint32_t bf[4][2];
            #pragma unroll
            for (int p = 0; p < 2; p++) {
                bf[2*p  ][0] = bb[p][0]; bf[2*p  ][1] = bb[p][2];
                bf[2*p+1][0] = bb[p][1]; bf[2*p+1][1] = bb[p][3];
            }
            #pragma unroll
            for (int mt = 0; mt < 4; mt++)
                #pragma unroll
                for (int nt = 0; nt < 4; nt++)
                    mma_bf16(c[mt][nt], a[mt], bf[nt]);
        }

        __syncthreads();   // all warps done reading slot s
        if (tid == 0 && it + STAGES < NKITER) {
            MBARRIER_EXPECT_TX(sb + s * 8, STAGE_BYTES);
            TMA_LOAD_2D(sb + SMEM_A_OFF + s * A_STAGE_BYTES, &tmapA, (it + STAGES) * TILE_K, m0, sb + s * 8);
            TMA_LOAD_2D(sb + SMEM_B_OFF + s * B_STAGE_BYTES, &tmapB, (it + STAGES) * TILE_K, v0, sb + s * 8);
        }
    }

    // ---- Epilogue: per-row (max, sum-exp) over this CTA's 32-col strip per warp ----
    const int g = lid >> 2;
    #pragma unroll
    for (int mt = 0; mt < 4; mt++) {
        #pragma unroll
        for (int half = 0; half < 2; half++) {
            float m = -INFINITY;
            #pragma unroll
            for (int nt = 0; nt < 4; nt++) {
                m = fmaxf(m, c[mt][nt][half * 2]);
                m = fmaxf(m, c[mt][nt][half * 2 + 1]);
            }
            float ssum = 0.f;
            #pragma unroll
            for (int nt = 0; nt < 4; nt++) {
                ssum += __expf(c[mt][nt][half * 2]     - m);
                ssum += __expf(c[mt][nt][half * 2 + 1] - m);
            }
            // quad reduce (lanes sharing the same row: lane%4 varies)
            #pragma unroll
            for (int off = 1; off <= 2; off <<= 1) {
                float om = __shfl_xor_sync(0xffffffffu, m, off);
                float os = __shfl_xor_sync(0xffffffffu, ssum, off);
                float nm = fmaxf(m, om);
                ssum = ssum * __expf(m - nm) + os * __expf(om - nm);
                m = nm;
            }
            if ((lid & 3) == 0) {
                int row = m0 + warp_m * WARP_M + mt * 16 + half * 8 + g;
                int pcol = vt * 4 + warp_n;
                g_part_m[pcol * N_TOK + row] = m;
                g_part_s[pcol * N_TOK + row] = ssum;
            }
        }
    }
}

// ============================================================
// Kernel 5: combine per-strip partials -> per-row NLL -> global sum
// ============================================================
__global__ void reduce_rows_kernel() {
    int n = blockIdx.x * blockDim.x + threadIdx.x;   // 8192 threads
    float nll = 0.f;
    int c = 0;
    if (n < N_TOK && g_valid[n]) {
        float m = -INFINITY;
        for (int j = 0; j < NV_P; j++) m = fmaxf(m, g_part_m[j * N_TOK + n]);
        float s = 0.f;
        for (int j = 0; j < NV_P; j++)
            s += g_part_s[j * N_TOK + n] * __expf(g_part_m[j * N_TOK + n] - m);
        nll = m + logf(s) - g_tgt_logit[n];
        c = 1;
    }
    #pragma unroll
    for (int o = 16; o; o >>= 1) {
        nll += __shfl_xor_sync(0xffffffffu, nll, o);
        c   += __shfl_xor_sync(0xffffffffu, c, o);
    }
    __shared__ float sm[8];
    __shared__ int   sc[8];
    if ((threadIdx.x & 31) == 0) { sm[threadIdx.x >> 5] = nll; sc[threadIdx.x >> 5] = c; }
    __syncthreads();
    if (threadIdx.x == 0) {
        float t = 0.f; int tc = 0;
        for (int w = 0; w < 8; w++) { t += sm[w]; tc += sc[w]; }
        atomicAdd(&g_sum, (double)t);
        atomicAdd(&g_cnt, tc);
    }
}

// ============================================================
// Kernel 6: final division
// ============================================================
__global__ void final_kernel(float* out) {
    out[0] = (g_cnt > 0) ? (float)(g_sum / (double)g_cnt) : 0.f;
}

// ============================================================
// Host launcher
// ============================================================
typedef CUresult (*PFN_encodeTiled)(
    CUtensorMap*, CUtensorMapDataType, cuuint32_t, void*,
    const cuuint64_t*, const cuuint64_t*, const cuuint32_t*, const cuuint32_t*,
    CUtensorMapInterleave, CUtensorMapSwizzle, CUtensorMapL2promotion, CUtensorMapFloatOOBfill);

extern "C" void kernel_launch(void* const* d_in, const int* in_sizes, int n_in,
                              void* d_out, int out_size) {
    const float* d_hidden  = (const float*)d_in[0];
    const void*  d_targets = d_in[1];
    const float* d_weight  = (const float*)d_in[2];
    float* out = (float*)d_out;

    void* pA = nullptr; cudaGetSymbolAddress(&pA, g_hbf);
    void* pB = nullptr; cudaGetSymbolAddress(&pB, g_wbf);

    PFN_encodeTiled encode = nullptr;
    {
        void* fp = nullptr;
        cudaDriverEntryPointQueryResult qres;
        cudaGetDriverEntryPoint("cuTensorMapEncodeTiled", &fp, cudaEnableDefault, &qres);
        encode = (PFN_encodeTiled)fp;
    }

    CUtensorMap mapA, mapB;
    {
        cuuint64_t dims[2]  = { DIM, N_TOK };
        cuuint64_t strd[1]  = { DIM * 2 };
        cuuint32_t box[2]   = { TILE_K, TILE_M };
        cuuint32_t es[2]    = { 1, 1 };
        encode(&mapA, CU_TENSOR_MAP_DATA_TYPE_BFLOAT16, 2, pA, dims, strd, box, es,
               CU_TENSOR_MAP_INTERLEAVE_NONE, CU_TENSOR_MAP_SWIZZLE_128B,
               CU_TENSOR_MAP_L2_PROMOTION_L2_128B, CU_TENSOR_MAP_FLOAT_OOB_FILL_NONE);
    }
    {
        cuuint64_t dims[2]  = { DIM, VOCAB };
        cuuint64_t strd[1]  = { DIM * 2 };
        cuuint32_t box[2]   = { TILE_K, TILE_V };
        cuuint32_t es[2]    = { 1, 1 };
        encode(&mapB, CU_TENSOR_MAP_DATA_TYPE_BFLOAT16, 2, pB, dims, strd, box, es,
               CU_TENSOR_MAP_INTERLEAVE_NONE, CU_TENSOR_MAP_SWIZZLE_128B,
               CU_TENSOR_MAP_L2_PROMOTION_L2_128B, CU_TENSOR_MAP_FLOAT_OOB_FILL_NONE);
    }

    cudaFuncSetAttribute(gemm_lse_kernel, cudaFuncAttributeMaxDynamicSharedMemorySize, SMEM_TOTAL);

    detect_zero_kernel<<<1, 32>>>((const int*)d_targets);
    convert_kernel<<<1184, 256>>>((const float4*)d_hidden, (const float4*)d_weight);
    tgt_logit_kernel<<<N_TOK, 256>>>(d_hidden, d_weight, d_targets);
    gemm_lse_kernel<<<dim3(NM_TILES, NV_TILES), 256, SMEM_TOTAL>>>(mapA, mapB);
    reduce_rows_kernel<<<32, 256>>>();
    final_kernel<<<1, 1>>>(out);
}

// round 8
// speedup vs baseline: 1.2151x; 1.0663x over previous
#include <cuda_runtime.h>
#include <cuda.h>
#include <cuda_bf16.h>
#include <math.h>
#include <stdint.h>

// ============================================================
// Problem constants
// ============================================================
#define IGNORE_INDEX (-100)
#define N_TOK   8192
#define DIM     2048
#define VOCAB   32000

#define TILE_M  128
#define TILE_V  128
#define TILE_K  64
#define NM_TILES (N_TOK / TILE_M)   // 64
#define NV_TILES (VOCAB / TILE_V)   // 250
#define NKITER   (DIM / TILE_K)     // 32
#define STAGES   3

// Per-warp tile: 64 (M) x 64 (V). 2x2 warp grid, 128 threads.
#define WARP_M 64
#define WARP_V 64
#define NV_P   (NV_TILES * 2)       // 500 vocab strips of 64 cols

#define A_STAGE_BYTES (TILE_M * TILE_K * 2)   // 16384
#define B_STAGE_BYTES (TILE_V * TILE_K * 2)   // 16384
#define STAGE_BYTES   (A_STAGE_BYTES + B_STAGE_BYTES)
#define SMEM_A_OFF 1024
#define SMEM_B_OFF (SMEM_A_OFF + STAGES * A_STAGE_BYTES)
#define SMEM_TOTAL (SMEM_B_OFF + STAGES * B_STAGE_BYTES)   // 99328 (~97KB) -> 2 CTAs/SM

// ============================================================
// Device-global scratch
// ============================================================
__device__ __nv_bfloat162 g_hbf[N_TOK * DIM / 2];     // 32 MB
__device__ __nv_bfloat162 g_wbf[VOCAB * DIM / 2];     // 131 MB
__device__ float g_part_m[NV_P * N_TOK];              // 16.4 MB
__device__ float g_part_s[NV_P * N_TOK];              // 16.4 MB
__device__ float g_tgt_logit[N_TOK];
__device__ int   g_valid[N_TOK];
__device__ int   g_is64;
__device__ double g_sum;
__device__ int    g_cnt;

// ============================================================
// PTX helpers
// ============================================================
__device__ __forceinline__ uint32_t smem_to_u32(const void* p) {
    uint32_t a;
    asm("{ .reg .u64 t; cvta.to.shared.u64 t, %1; cvt.u32.u64 %0, t; }" : "=r"(a) : "l"(p));
    return a;
}

#define MBARRIER_INIT(addr, cnt) \
    asm volatile("mbarrier.init.shared.b64 [%0], %1;" :: "r"((uint32_t)(addr)), "r"((uint32_t)(cnt)) : "memory")
#define MBARRIER_EXPECT_TX(addr, tx) \
    asm volatile("mbarrier.arrive.expect_tx.shared.b64 _, [%0], %1;" :: "r"((uint32_t)(addr)), "r"((uint32_t)(tx)) : "memory")

#define MBARRIER_WAIT_PARITY(mbar_smem_addr, phase_parity) do { \
    uint32_t _mbar = (uint32_t)(mbar_smem_addr); \
    uint32_t _parity = (uint32_t)(phase_parity); \
    uint32_t _done; \
    asm volatile("{\n\t.reg .pred p;\n\t" \
        "mbarrier.try_wait.parity.acquire.cta.shared::cta.b64 p, [%1], %2;\n\t" \
        "selp.b32 %0, 1, 0, p;\n\t}" \
        : "=r"(_done) : "r"(_mbar), "r"(_parity) : "memory"); \
    if (!_done) { \
        asm volatile("{\n\t.reg .pred P1;\n\t" \
            "WAIT_LOOP_%=:\n\t" \
            "mbarrier.try_wait.parity.acquire.cta.shared::cta.b64 P1, [%0], %1, 0x989680;\n\t" \
            "@P1 bra.uni WAIT_DONE_%=;\n\t" \
            "bra.uni WAIT_LOOP_%=;\n\t" \
            "WAIT_DONE_%=:\n\t}" \
            :: "r"(_mbar), "r"(_parity) : "memory"); \
    } \
} while(0)

#define TMA_LOAD_2D(smem_addr, map_ptr, cx, cy, mbar) \
    asm volatile("cp.async.bulk.tensor.2d.shared::cta.global.tile.mbarrier::complete_tx::bytes " \
        "[%0], [%1, {%2, %3}], [%4];" \
        :: "r"((uint32_t)(smem_addr)), "l"(map_ptr), "r"((int)(cx)), "r"((int)(cy)), \
           "r"((uint32_t)(mbar)) : "memory")

__device__ __forceinline__ void ldmatrix_x4(uint32_t& r0, uint32_t& r1, uint32_t& r2, uint32_t& r3,
                                            uint32_t addr) {
    asm volatile("ldmatrix.sync.aligned.m8n8.x4.shared.b16 {%0,%1,%2,%3}, [%4];"
        : "=r"(r0), "=r"(r1), "=r"(r2), "=r"(r3) : "r"(addr));
}

__device__ __forceinline__ void mma_bf16(float* c, const uint32_t* a, uint32_t b0, uint32_t b1) {
    asm volatile("mma.sync.aligned.m16n8k16.row.col.f32.bf16.bf16.f32 "
        "{%0,%1,%2,%3}, {%4,%5,%6,%7}, {%8,%9}, {%0,%1,%2,%3};"
        : "+f"(c[0]), "+f"(c[1]), "+f"(c[2]), "+f"(c[3])
        : "r"(a[0]), "r"(a[1]), "r"(a[2]), "r"(a[3]), "r"(b0), "r"(b1));
}

// ============================================================
// Kernel 1: detect target dtype (int64 vs int32) + zero accumulators
// ============================================================
__global__ void detect_zero_kernel(const int* t32) {
    if (threadIdx.x == 0) {
        int is64 = 1;
        for (int i = 1; i < 512; i += 2) {
            int v = t32[i];
            if (v != 0 && v != -1) { is64 = 0; break; }
        }
        g_is64 = is64;
        g_sum = 0.0;
        g_cnt = 0;
    }
}

// ============================================================
// Kernel 2: fp32 -> bf16 conversion of hidden + weight
// ============================================================
__global__ void convert_kernel(const float4* __restrict__ h, const float4* __restrict__ w) {
    const int NH4 = N_TOK * DIM / 4;
    const int NW4 = VOCAB * DIM / 4;
    for (int i = blockIdx.x * blockDim.x + threadIdx.x; i < NH4 + NW4;
         i += gridDim.x * blockDim.x) {
        float4 v;
        __nv_bfloat162* dst;
        if (i < NH4) { v = h[i]; dst = &g_hbf[i * 2]; }
        else         { int j = i - NH4; v = w[j]; dst = &g_wbf[j * 2]; }
        dst[0] = __floats2bfloat162_rn(v.x, v.y);
        dst[1] = __floats2bfloat162_rn(v.z, v.w);
    }
}

// ============================================================
// Kernel 3: exact fp32 target logit per token
// ============================================================
__global__ void tgt_logit_kernel(const float* __restrict__ hidden,
                                 const float* __restrict__ weight,
                                 const void* __restrict__ targets) {
    int n = blockIdx.x;
    long long t;
    if (g_is64) t = ((const long long*)targets)[n];
    else        t = (long long)((const int*)targets)[n];
    bool valid = (t != IGNORE_INDEX) && (t >= 0) && (t < VOCAB);
    if (!valid) {
        if (threadIdx.x == 0) { g_tgt_logit[n] = 0.f; g_valid[n] = 0; }
        return;
    }
    const float4* hv = (const float4*)(hidden + (size_t)n * DIM);
    const float4* wv = (const float4*)(weight + (size_t)t * DIM);
    float acc = 0.f;
    for (int i = threadIdx.x; i < DIM / 4; i += blockDim.x) {
        float4 a = hv[i], b = wv[i];
        acc += a.x * b.x + a.y * b.y + a.z * b.z + a.w * b.w;
    }
    #pragma unroll
    for (int o = 16; o; o >>= 1) acc += __shfl_xor_sync(0xffffffffu, acc, o);
    __shared__ float ws[8];
    if ((threadIdx.x & 31) == 0) ws[threadIdx.x >> 5] = acc;
    __syncthreads();
    if (threadIdx.x == 0) {
        float s = 0.f;
        for (int w2 = 0; w2 < (int)(blockDim.x >> 5); w2++) s += ws[w2];
        g_tgt_logit[n] = s;
        g_valid[n] = 1;
    }
}

// ============================================================
// Kernel 4: TMA-pipelined bf16 HMMA GEMM (128x128x64) + fused online LSE
//   - 4 warps, 64x64 warp tile (8 ldmatrix : 32 MMA per ks-step)
//   - swizzle folded into lane constants; no modulo in the loop
//   - 3 stages, 2 CTAs/SM
// ============================================================
__global__ __launch_bounds__(128, 2)
void gemm_lse_kernel(const __grid_constant__ CUtensorMap tmapA,
                     const __grid_constant__ CUtensorMap tmapB) {
    extern __shared__ char smem[];
    const uint32_t sb = smem_to_u32(smem);
    const int tid = threadIdx.x;
    const int wid = tid >> 5;
    const int lid = tid & 31;
    const int warp_m = wid >> 1;          // 0..1
    const int warp_n = wid & 1;           // 0..1

    if (tid == 0) {
        #pragma unroll
        for (int s = 0; s < STAGES; s++) MBARRIER_INIT(sb + s * 8, 1);
    }
    __syncthreads();

    const int m0 = blockIdx.x * TILE_M;
    const int vt = blockIdx.y;
    const int v0 = vt * TILE_V;

    // Prologue: fill all stages
    if (tid == 0) {
        #pragma unroll
        for (int s = 0; s < STAGES; s++) {
            MBARRIER_EXPECT_TX(sb + s * 8, STAGE_BYTES);
            TMA_LOAD_2D(sb + SMEM_A_OFF + s * A_STAGE_BYTES, &tmapA, s * TILE_K, m0, sb + s * 8);
            TMA_LOAD_2D(sb + SMEM_B_OFF + s * B_STAGE_BYTES, &tmapB, s * TILE_K, v0, sb + s * 8);
        }
    }

    // Lane constants. For off = row*128 + col2: SW128(off) = row*128 + (col2 ^ ((row&7)<<4)).
    const int tIdx = lid >> 3;            // 0..3
    const int rIn  = lid & 7;
    const int rowA0 = warp_m * WARP_M + (tIdx & 1) * 8 + rIn;   // + mt*16
    const int rowB0 = warp_n * WARP_V + (tIdx & 1) * 8 + rIn;   // + p*16
    const int colHalf2 = (tIdx >> 1) * 16;                       // byte offset of 8-col half

    const uint32_t xorA = (uint32_t)((rowA0 & 7) << 4);
    const uint32_t xorB = (uint32_t)((rowB0 & 7) << 4);
    uint32_t cA[4], cB[4];
    #pragma unroll
    for (int ks = 0; ks < 4; ks++) {
        cA[ks] = ((uint32_t)(ks * 32 + colHalf2)) ^ xorA;
        cB[ks] = ((uint32_t)(ks * 32 + colHalf2)) ^ xorB;
    }
    const uint32_t aLane = sb + SMEM_A_OFF + (uint32_t)rowA0 * 128;
    const uint32_t bLane = sb + SMEM_B_OFF + (uint32_t)rowB0 * 128;

    float c[4][8][4];
    #pragma unroll
    for (int i = 0; i < 4; i++)
        #pragma unroll
        for (int j = 0; j < 8; j++)
            #pragma unroll
            for (int q = 0; q < 4; q++) c[i][j][q] = 0.f;

    int s = 0, ph = 0;
    for (int it = 0; it < NKITER; it++) {
        MBARRIER_WAIT_PARITY(sb + s * 8, ph);

        const uint32_t aS = aLane + s * A_STAGE_BYTES;
        const uint32_t bS = bLane + s * B_STAGE_BYTES;

        #pragma unroll
        for (int ks = 0; ks < TILE_K / 16; ks++) {
            // A fragments: 4 m-tiles (64 rows)
            uint32_t a[4][4];
            #pragma unroll
            for (int mt = 0; mt < 4; mt++)
                ldmatrix_x4(a[mt][0], a[mt][1], a[mt][2], a[mt][3],
                            aS + (uint32_t)(mt * 16 * 128) + cA[ks]);
            // B fragments: 4 pair-loads covering 8 n-tiles (64 cols)
            uint32_t bb[4][4];
            #pragma unroll
            for (int p = 0; p < 4; p++)
                ldmatrix_x4(bb[p][0], bb[p][1], bb[p][2], bb[p][3],
                            bS + (uint32_t)(p * 16 * 128) + cB[ks]);
            #pragma unroll
            for (int mt = 0; mt < 4; mt++)
                #pragma unroll
                for (int p = 0; p < 4; p++) {
                    mma_bf16(c[mt][2*p    ], a[mt], bb[p][0], bb[p][2]);
                    mma_bf16(c[mt][2*p + 1], a[mt], bb[p][1], bb[p][3]);
                }
        }

        __syncthreads();   // all warps done reading slot s
        if (tid == 0 && it + STAGES < NKITER) {
            MBARRIER_EXPECT_TX(sb + s * 8, STAGE_BYTES);
            TMA_LOAD_2D(sb + SMEM_A_OFF + s * A_STAGE_BYTES, &tmapA, (it + STAGES) * TILE_K, m0, sb + s * 8);
            TMA_LOAD_2D(sb + SMEM_B_OFF + s * B_STAGE_BYTES, &tmapB, (it + STAGES) * TILE_K, v0, sb + s * 8);
        }
        if (++s == STAGES) { s = 0; ph ^= 1; }
    }

    // ---- Epilogue: per-row (max, sum-exp) over this warp's 64-col strip ----
    const int g = lid >> 2;
    #pragma unroll
    for (int mt = 0; mt < 4; mt++) {
        #pragma unroll
        for (int half = 0; half < 2; half++) {
            float m = -INFINITY;
            #pragma unroll
            for (int nt = 0; nt < 8; nt++) {
                m = fmaxf(m, c[mt][nt][half * 2]);
                m = fmaxf(m, c[mt][nt][half * 2 + 1]);
            }
            float ssum = 0.f;
            #pragma unroll
            for (int nt = 0; nt < 8; nt++) {
                ssum += __expf(c[mt][nt][half * 2]     - m);
                ssum += __expf(c[mt][nt][half * 2 + 1] - m);
            }
            // quad reduce (lanes sharing the same row: lane%4 varies)
            #pragma unroll
            for (int off = 1; off <= 2; off <<= 1) {
                float om = __shfl_xor_sync(0xffffffffu, m, off);
                float os = __shfl_xor_sync(0xffffffffu, ssum, off);
                float nm = fmaxf(m, om);
                ssum = ssum * __expf(m - nm) + os * __expf(om - nm);
                m = nm;
            }
            if ((lid & 3) == 0) {
                int row = m0 + warp_m * WARP_M + mt * 16 + half * 8 + g;
                int pcol = vt * 2 + warp_n;
                g_part_m[pcol * N_TOK + row] = m;
                g_part_s[pcol * N_TOK + row] = ssum;
            }
        }
    }
}

// ============================================================
// Kernel 5: combine per-strip partials -> per-row NLL -> global sum
// ============================================================
__global__ void reduce_rows_kernel() {
    int n = blockIdx.x * blockDim.x + threadIdx.x;   // 8192 threads
    float nll = 0.f;
    int c = 0;
    if (n < N_TOK && g_valid[n]) {
        float m = -INFINITY;
        for (int j = 0; j < NV_P; j++) m = fmaxf(m, g_part_m[j * N_TOK + n]);
        float s = 0.f;
        for (int j = 0; j < NV_P; j++)
            s += g_part_s[j * N_TOK + n] * __expf(g_part_m[j * N_TOK + n] - m);
        nll = m + logf(s) - g_tgt_logit[n];
        c = 1;
    }
    #pragma unroll
    for (int o = 16; o; o >>= 1) {
        nll += __shfl_xor_sync(0xffffffffu, nll, o);
        c   += __shfl_xor_sync(0xffffffffu, c, o);
    }
    __shared__ float sm[8];
    __shared__ int   sc[8];
    if ((threadIdx.x & 31) == 0) { sm[threadIdx.x >> 5] = nll; sc[threadIdx.x >> 5] = c; }
    __syncthreads();
    if (threadIdx.x == 0) {
        float t = 0.f; int tc = 0;
        for (int w = 0; w < 8; w++) { t += sm[w]; tc += sc[w]; }
        atomicAdd(&g_sum, (double)t);
        atomicAdd(&g_cnt, tc);
    }
}

// ============================================================
// Kernel 6: final division
// ============================================================
__global__ void final_kernel(float* out) {
    out[0] = (g_cnt > 0) ? (float)(g_sum / (double)g_cnt) : 0.f;
}

// ============================================================
// Host launcher
// ============================================================
typedef CUresult (*PFN_encodeTiled)(
    CUtensorMap*, CUtensorMapDataType, cuuint32_t, void*,
    const cuuint64_t*, const cuuint64_t*, const cuuint32_t*, const cuuint32_t*,
    CUtensorMapInterleave, CUtensorMapSwizzle, CUtensorMapL2promotion, CUtensorMapFloatOOBfill);

extern "C" void kernel_launch(void* const* d_in, const int* in_sizes, int n_in,
                              void* d_out, int out_size) {
    const float* d_hidden  = (const float*)d_in[0];
    const void*  d_targets = d_in[1];
    const float* d_weight  = (const float*)d_in[2];
    float* out = (float*)d_out;

    void* pA = nullptr; cudaGetSymbolAddress(&pA, g_hbf);
    void* pB = nullptr; cudaGetSymbolAddress(&pB, g_wbf);

    PFN_encodeTiled encode = nullptr;
    {
        void* fp = nullptr;
        cudaDriverEntryPointQueryResult qres;
        cudaGetDriverEntryPoint("cuTensorMapEncodeTiled", &fp, cudaEnableDefault, &qres);
        encode = (PFN_encodeTiled)fp;
    }

    CUtensorMap mapA, mapB;
    {
        cuuint64_t dims[2]  = { DIM, N_TOK };
        cuuint64_t strd[1]  = { DIM * 2 };
        cuuint32_t box[2]   = { TILE_K, TILE_M };
        cuuint32_t es[2]    = { 1, 1 };
        encode(&mapA, CU_TENSOR_MAP_DATA_TYPE_BFLOAT16, 2, pA, dims, strd, box, es,
               CU_TENSOR_MAP_INTERLEAVE_NONE, CU_TENSOR_MAP_SWIZZLE_128B,
               CU_TENSOR_MAP_L2_PROMOTION_L2_128B, CU_TENSOR_MAP_FLOAT_OOB_FILL_NONE);
    }
    {
        cuuint64_t dims[2]  = { DIM, VOCAB };
        cuuint64_t strd[1]  = { DIM * 2 };
        cuuint32_t box[2]   = { TILE_K, TILE_V };
        cuuint32_t es[2]    = { 1, 1 };
        encode(&mapB, CU_TENSOR_MAP_DATA_TYPE_BFLOAT16, 2, pB, dims, strd, box, es,
               CU_TENSOR_MAP_INTERLEAVE_NONE, CU_TENSOR_MAP_SWIZZLE_128B,
               CU_TENSOR_MAP_L2_PROMOTION_L2_128B, CU_TENSOR_MAP_FLOAT_OOB_FILL_NONE);
    }

    cudaFuncSetAttribute(gemm_lse_kernel, cudaFuncAttributeMaxDynamicSharedMemorySize, SMEM_TOTAL);

    detect_zero_kernel<<<1, 32>>>((const int*)d_targets);
    convert_kernel<<<1184, 256>>>((const float4*)d_hidden, (const float4*)d_weight);
    tgt_logit_kernel<<<N_TOK, 256>>>(d_hidden, d_weight, d_targets);
    gemm_lse_kernel<<<dim3(NM_TILES, NV_TILES), 128, SMEM_TOTAL>>>(mapA, mapB);
    reduce_rows_kernel<<<32, 256>>>();
    final_kernel<<<1, 1>>>(out);
}